// round 9
// baseline (speedup 1.0000x reference)
#include <cuda_runtime.h>
#include <cuda_bf16.h>
#include <math.h>
#include <stdint.h>

#define DD 256
#define MAXN 4096
#define MAXV 50432
#define MAX_NORM (1.0f - 1e-5f)
#define EPSF 1e-7f

#define BM 128
#define BN 128
#define BK 64
#define SSTRIDE 72            // bf16/row (64+8 pad) -> conflict-free ldmatrix

#define PER_STAGE (BM * SSTRIDE * 2)    // 18432 B
#define WG_BYTES  (4 * PER_STAGE)       // A s0,s1 + B s0,s1 = 73728 B per WG
#define OFF_SC    (2 * WG_BYTES)        // 147456
#define CSTRIDE   132
#define OFF_SH    (OFF_SC + BM * CSTRIDE * 4)   // 147456 + 67584 = 215040
#define SMEM_TOTAL (OFF_SH + BM * 8)            // 216064

// ---- scratch (__device__ globals: allocation-free rule) ----
static __device__ __nv_bfloat16 g_hb[(size_t)MAXN * DD];
static __device__ __nv_bfloat16 g_vb[(size_t)MAXV * DD];
static __device__ float2 g_h2a[MAXN];   // (h2, 2/(1-h2))
static __device__ float2 g_v2b[MAXV];   // (v2, 1/(1-v2))

// ---------------- PTX helpers ----------------
__device__ __forceinline__ uint32_t smem_u32(const void* p) {
    return (uint32_t)__cvta_generic_to_shared(p);
}
__device__ __forceinline__ void cp16(uint32_t dst, const void* src, bool pred) {
    asm volatile("cp.async.cg.shared.global [%0], [%1], 16, %2;"
                 :: "r"(dst), "l"(src), "r"(pred ? 16u : 0u) : "memory");
}
__device__ __forceinline__ void cp_commit() {
    asm volatile("cp.async.commit_group;" ::: "memory");
}
template <int NN>
__device__ __forceinline__ void cp_wait() {
    asm volatile("cp.async.wait_group %0;" :: "n"(NN) : "memory");
}
__device__ __forceinline__ void ldsm_x4(uint32_t* r, uint32_t addr) {
    asm volatile("ldmatrix.sync.aligned.m8n8.x4.shared.b16 {%0,%1,%2,%3}, [%4];"
                 : "=r"(r[0]), "=r"(r[1]), "=r"(r[2]), "=r"(r[3]) : "r"(addr));
}
__device__ __forceinline__ void mma16816(float* c, const uint32_t* a,
                                         uint32_t b0, uint32_t b1) {
    asm volatile(
        "mma.sync.aligned.m16n8k16.row.col.f32.bf16.bf16.f32 "
        "{%0,%1,%2,%3}, {%4,%5,%6,%7}, {%8,%9}, {%0,%1,%2,%3};"
        : "+f"(c[0]), "+f"(c[1]), "+f"(c[2]), "+f"(c[3])
        : "r"(a[0]), "r"(a[1]), "r"(a[2]), "r"(a[3]), "r"(b0), "r"(b1));
}
__device__ __forceinline__ void stcs1(float* p, float x) {
    asm volatile("st.global.cs.f32 [%0], %1;" :: "l"(p), "f"(x) : "memory");
}
// ---- packed f32x2 ----
__device__ __forceinline__ uint64_t pk2(float lo, float hi) {
    uint64_t r; asm("mov.b64 %0, {%1, %2};" : "=l"(r) : "f"(lo), "f"(hi)); return r;
}
__device__ __forceinline__ void upk2(float& lo, float& hi, uint64_t v) {
    asm("mov.b64 {%0, %1}, %2;" : "=f"(lo), "=f"(hi) : "l"(v));
}
__device__ __forceinline__ uint64_t add2(uint64_t a, uint64_t b) {
    uint64_t r; asm("add.rn.f32x2 %0, %1, %2;" : "=l"(r) : "l"(a), "l"(b)); return r;
}
__device__ __forceinline__ uint64_t mul2(uint64_t a, uint64_t b) {
    uint64_t r; asm("mul.rn.f32x2 %0, %1, %2;" : "=l"(r) : "l"(a), "l"(b)); return r;
}
__device__ __forceinline__ uint64_t fma2p(uint64_t a, uint64_t b, uint64_t c) {
    uint64_t r; asm("fma.rn.f32x2 %0, %1, %2, %3;" : "=l"(r) : "l"(a), "l"(b), "l"(c));
    return r;
}

// ---------------------------------------------------------------------------
template <bool IS_H>
__global__ void proj_kernel(const float* __restrict__ in, int rows) {
    const int row = blockIdx.x * 8 + (threadIdx.x >> 5);
    const int lane = threadIdx.x & 31;
    if (row >= rows) return;

    const float4* p = reinterpret_cast<const float4*>(in) + (size_t)row * (DD / 4) + lane * 2;
    float4 x0 = p[0], x1 = p[1];
    float s = x0.x * x0.x + x0.y * x0.y + x0.z * x0.z + x0.w * x0.w +
              x1.x * x1.x + x1.y * x1.y + x1.z * x1.z + x1.w * x1.w;
    #pragma unroll
    for (int o = 16; o > 0; o >>= 1) s += __shfl_xor_sync(0xffffffffu, s, o);

    const float norm = sqrtf(s);
    const float scale = (norm > MAX_NORM) ? (MAX_NORM / fmaxf(norm, EPSF)) : 1.0f;
    const float n2 = s * scale * scale;

    __nv_bfloat16 ob[8];
    ob[0] = __float2bfloat16(x0.x * scale); ob[1] = __float2bfloat16(x0.y * scale);
    ob[2] = __float2bfloat16(x0.z * scale); ob[3] = __float2bfloat16(x0.w * scale);
    ob[4] = __float2bfloat16(x1.x * scale); ob[5] = __float2bfloat16(x1.y * scale);
    ob[6] = __float2bfloat16(x1.z * scale); ob[7] = __float2bfloat16(x1.w * scale);

    __nv_bfloat16* dst = (IS_H ? g_hb : g_vb) + (size_t)row * DD + lane * 8;
    *reinterpret_cast<uint4*>(dst) = *reinterpret_cast<const uint4*>(ob);

    if (lane == 0) {
        if (IS_H) g_h2a[row] = make_float2(n2, 2.0f / (1.0f - n2));
        else      g_v2b[row] = make_float2(n2, 1.0f / (1.0f - n2));
    }
}

// ---------------------------------------------------------------------------
// Persistent ping-pong kernel: 512 threads = 2 warpgroups; each WG owns its
// 2-stage operand buffers and processes alternate tiles; the shared sC
// epilogue buffer is guarded by cross-WG named barriers (BAR3/BAR4),
// enforcing anti-phase: one WG's epilogue overlaps the other's mainloop.
// ---------------------------------------------------------------------------
__global__ void __launch_bounds__(512, 1)
hyp_gemm_pp(float* __restrict__ out, int N, int V, int numM, int total, int nslot) {
    extern __shared__ __align__(16) char smem[];
    const int tid = threadIdx.x;
    const int wg = tid >> 8;            // 0 / 1
    const int wg_tid = tid & 255;
    const int wid = wg_tid >> 5;        // 0..7 within WG
    const int lane = tid & 31;
    const int wm = wid & 3;
    const int wn = wid >> 2;

    const uint32_t sA0 = smem_u32(smem) + (uint32_t)wg * WG_BYTES;
    const uint32_t sB0 = sA0 + 2 * PER_STAGE;
    float* sC = reinterpret_cast<float*>(smem + OFF_SC);
    float2* sH = reinterpret_cast<float2*>(smem + OFF_SH);

    const int slot = blockIdx.x * 2 + wg;
    const int slot0 = blockIdx.x * 2;
    const int iters = (total > slot0) ? (total - slot0 + nslot - 1) / nslot : 0;

    const int cr = wg_tid >> 3;         // 0..31
    const int cc = wg_tid & 7;          // 16B column 0..7
    const int aRowBase = wm * 32 + (lane & 15);
    const int aColSel  = (lane >> 4) * 8;
    const int bRowBase = wn * 64 + (lane & 7) + ((lane >> 4) << 3);
    const int bColSel  = ((lane >> 3) & 1) * 8;

    auto prefetch = [&](int stage, int row0, int col0, int k0) {
        #pragma unroll
        for (int i = 0; i < 4; i++) {
            const int r = cr + i * 32;
            const uint32_t so = (uint32_t)(r * SSTRIDE + cc * 8) * 2;
            cp16(sA0 + stage * PER_STAGE + so,
                 &g_hb[(size_t)(row0 + r) * DD + k0 + cc * 8], (row0 + r) < N);
            const int vr = col0 + r;
            const bool ok = vr < V;
            cp16(sB0 + stage * PER_STAGE + so,
                 &g_vb[(size_t)(ok ? vr : 0) * DD + k0 + cc * 8], ok);
        }
        cp_commit();
    };

    float acc[2][8][4];

    auto compute_stage = [&](int stage) {
        const uint32_t aBase = sA0 + stage * PER_STAGE;
        const uint32_t bBase = sB0 + stage * PER_STAGE;
        #pragma unroll
        for (int kp = 0; kp < 4; kp++) {
            uint32_t a[2][4];
            #pragma unroll
            for (int mt = 0; mt < 2; mt++) {
                const uint32_t ad = aBase +
                    (uint32_t)((aRowBase + mt * 16) * SSTRIDE + kp * 16 + aColSel) * 2;
                ldsm_x4(a[mt], ad);
            }
            uint32_t b[4][4];
            #pragma unroll
            for (int np = 0; np < 4; np++) {
                const uint32_t bd = bBase +
                    (uint32_t)((bRowBase + np * 16) * SSTRIDE + kp * 16 + bColSel) * 2;
                ldsm_x4(b[np], bd);
            }
            #pragma unroll
            for (int mt = 0; mt < 2; mt++)
                #pragma unroll
                for (int nt = 0; nt < 8; nt++)
                    mma16816(acc[mt][nt], a[mt],
                             b[nt >> 1][(nt & 1) * 2], b[nt >> 1][(nt & 1) * 2 + 1]);
        }
    };

    const int barwg_id = 1 + wg;        // named barrier per WG (256 threads)
    #define BARWG() asm volatile("bar.sync %0, 256;" :: "r"(barwg_id) : "memory")

    // -arccosh(1+t) = sqrt(2t) * (-P(t)) Taylor coefficients (Horner)
    const uint64_t C0 = pk2(-1.0f, -1.0f);
    const uint64_t C1 = pk2(1.0f / 12.0f, 1.0f / 12.0f);
    const uint64_t C2 = pk2(-3.0f / 160.0f, -3.0f / 160.0f);
    const uint64_t C3 = pk2(5.0f / 896.0f, 5.0f / 896.0f);
    const uint64_t C4 = pk2(-35.0f / 18432.0f, -35.0f / 18432.0f);
    const uint64_t C5 = pk2(63.0f / 90112.0f, 63.0f / 90112.0f);
    const uint64_t NEG2 = pk2(-2.0f, -2.0f);

    // Prologue: prefetch first tile; WG1 primes BAR3 (sC initially free for WG0)
    {
        const int id0 = slot;
        if (id0 < total) {
            const int r0 = (id0 % numM) * BM, c0 = (id0 / numM) * BN;
            prefetch(0, r0, c0, 0);
            prefetch(1, r0, c0, BK);
        }
    }
    if (wg == 1) asm volatile("bar.arrive 3, 512;" ::: "memory");

    for (int i = 0; i < iters; i++) {
        const int id = slot + i * nslot;
        const bool active = id < total;
        const int idc = active ? id : 0;
        const int row0 = (idc % numM) * BM;
        const int col0 = (idc / numM) * BN;

        #pragma unroll
        for (int mt = 0; mt < 2; mt++)
            #pragma unroll
            for (int nt = 0; nt < 8; nt++)
                #pragma unroll
                for (int q = 0; q < 4; q++) acc[mt][nt][q] = 0.f;

        // ---- mainloop: K=256 in 4 chunks, 2-stage double buffer ----
        cp_wait<1>(); BARWG();                       // s0 ready for all
        compute_stage(0);
        cp_wait<0>(); BARWG();                       // s1 ready; s0 reads done
        if (active) prefetch(0, row0, col0, 2 * BK);
        compute_stage(1);
        cp_wait<0>(); BARWG();                       // s0(k128) ready; s1 reads done
        if (active) prefetch(1, row0, col0, 3 * BK);
        compute_stage(0);
        cp_wait<0>(); BARWG();                       // s1(k192) ready
        compute_stage(1);

        // ---- acquire shared sC (blocks this WG until peer released it);
        //      also acts as this WG's internal barrier (all compute done) ----
        if (wg == 0) asm volatile("bar.sync 3, 512;" ::: "memory");
        else         asm volatile("bar.sync 4, 512;" ::: "memory");

        // stage accumulators + per-row h2a into sC/sH
        const int g = lane >> 2;
        const int tg = lane & 3;
        #pragma unroll
        for (int mt = 0; mt < 2; mt++) {
            #pragma unroll
            for (int nt = 0; nt < 8; nt++) {
                const int cl = wn * 64 + nt * 8 + tg * 2;
                #pragma unroll
                for (int rh = 0; rh < 2; rh++) {
                    const int rl = wm * 32 + mt * 16 + g + rh * 8;
                    *reinterpret_cast<float2*>(&sC[rl * CSTRIDE + cl]) =
                        make_float2(acc[mt][nt][rh * 2 + 0], acc[mt][nt][rh * 2 + 1]);
                }
            }
        }
        if (wg_tid < BM) sH[wg_tid] = g_h2a[row0 + wg_tid];

        // prefetch this WG's NEXT tile (stages are free: mainloop done)
        {
            const int idn = id + nslot;
            if (idn < total) {
                const int r0n = (idn % numM) * BM, c0n = (idn / numM) * BN;
                prefetch(0, r0n, c0n, 0);
                prefetch(1, r0n, c0n, BK);
            }
        }
        BARWG();                                     // sC/sH staged & visible

        // ---- coalesced packed epilogue: thread owns one column ----
        const int coll = wg_tid & 127;
        const int hi = wg_tid >> 7;
        const int c = col0 + coll;
        const bool colok = active && (c < V);
        const float2 vb = colok ? g_v2b[c] : make_float2(0.f, 1.f);
        const uint64_t VBX2 = pk2(vb.x, vb.x);
        const uint64_t VBY2 = pk2(vb.y, vb.y);

        #pragma unroll 4
        for (int it = 0; it < 32; it++) {
            const int rl0 = it * 4 + hi * 2;
            const int rl1 = rl0 + 1;
            const float2 ha0 = sH[rl0];
            const float2 ha1 = sH[rl1];
            const float d0 = sC[rl0 * CSTRIDE + coll];
            const float d1 = sC[rl1 * CSTRIDE + coll];

            uint64_t D2 = pk2(d0, d1);
            uint64_t H2 = pk2(ha0.x, ha1.x);
            uint64_t A2 = pk2(ha0.y, ha1.y);

            uint64_t sq2 = fma2p(NEG2, D2, add2(H2, VBX2));
            uint64_t t2 = mul2(sq2, mul2(A2, VBY2));

            float t0, t1;
            upk2(t0, t1, t2);
            t0 = fmaxf(t0, 1e-7f);
            t1 = fmaxf(t1, 1e-7f);
            t2 = pk2(t0, t1);

            uint64_t p = fma2p(C5, t2, C4);
            p = fma2p(p, t2, C3);
            p = fma2p(p, t2, C2);
            p = fma2p(p, t2, C1);
            p = fma2p(p, t2, C0);

            float s0, s1;
            asm("sqrt.approx.f32 %0, %1;" : "=f"(s0) : "f"(t0 + t0));
            asm("sqrt.approx.f32 %0, %1;" : "=f"(s1) : "f"(t1 + t1));

            uint64_t O2 = mul2(pk2(s0, s1), p);
            float o0, o1;
            upk2(o0, o1, O2);

            if (colok) {
                stcs1(&out[(size_t)(row0 + rl0) * V + c], o0);
                stcs1(&out[(size_t)(row0 + rl1) * V + c], o1);
            }
        }

        // ---- release sC to the peer WG ----
        if (wg == 0) asm volatile("bar.arrive 4, 512;" ::: "memory");
        else         asm volatile("bar.arrive 3, 512;" ::: "memory");
    }
    #undef BARWG
}

// ---------------------------------------------------------------------------
extern "C" void kernel_launch(void* const* d_in, const int* in_sizes, int n_in,
                              void* d_out, int out_size) {
    const float* hs = (const float*)d_in[0];   // hidden_states [N, 256]
    const float* ve = (const float*)d_in[1];   // vocab_embeddings [V, 256]
    const int N = in_sizes[0] / DD;            // 4096
    const int V = in_sizes[1] / DD;            // 50257

    proj_kernel<true><<<(N + 7) / 8, 256>>>(hs, N);
    proj_kernel<false><<<(V + 7) / 8, 256>>>(ve, V);

    static int nsm = 0;
    if (!nsm) {
        if (cudaDeviceGetAttribute(&nsm, cudaDevAttrMultiProcessorCount, 0)
                != cudaSuccess || nsm <= 0)
            nsm = 148;
        cudaFuncSetAttribute(hyp_gemm_pp,
                             cudaFuncAttributeMaxDynamicSharedMemorySize, SMEM_TOTAL);
    }
    const int numM = (N + BM - 1) / BM;
    const int numN = (V + BN - 1) / BN;
    const int total = numM * numN;
    const int nslot = 2 * nsm;

    hyp_gemm_pp<<<nsm, 512, SMEM_TOTAL>>>((float*)d_out, N, V, numM, total, nslot);
}